// round 1
// baseline (speedup 1.0000x reference)
#include <cuda_runtime.h>
#include <cuda_bf16.h>

// Problem constants
constexpr int B  = 4;
constexpr int N  = 2048;
constexpr int D  = 512;
constexpr int H  = 8;
constexpr int DH = 64;
constexpr float SCALE = 0.125f;        // DH^-0.5 = 1/8

constexpr int M_ROWS   = B * N;        // 8192
constexpr int QKV_COLS = 3 * H * DH;   // 1536

// Scratch: Q/K/V in [B][H][N][DH] layout (static device arrays; no allocations)
__device__ float g_Q[(size_t)B * H * N * DH];
__device__ float g_K[(size_t)B * H * N * DH];
__device__ float g_V[(size_t)B * H * N * DH];

// ---------------------------------------------------------------------------
// Kernel 1: QKV projection GEMM.
// C[m][c] = sum_k X[m][k] * W[c][k]   (X: [8192,512], W: [1536,512] row-major)
// 128x128x8 tiles, 256 threads, 8x8 per-thread microtile.
// Epilogue scatters column c -> (which, h, dh) into g_Q / g_K / g_V.
// ---------------------------------------------------------------------------
__global__ __launch_bounds__(256) void qkv_gemm(const float* __restrict__ X,
                                                const float* __restrict__ W)
{
    constexpr int BM = 128, BN = 128, BK = 8;
    constexpr int PAD = 4;
    __shared__ float sA[BK][BM + PAD];
    __shared__ float sB[BK][BN + PAD];

    const int tid = threadIdx.x;
    const int m0  = blockIdx.y * BM;
    const int n0  = blockIdx.x * BN;

    const int tx = tid & 15;   // 0..15 -> N direction
    const int ty = tid >> 4;   // 0..15 -> M direction

    // Global load mapping: each thread loads one float4 of A and one of B
    const int lrow  = tid >> 1;        // 0..127
    const int lcol4 = (tid & 1) * 4;   // 0 or 4

    float acc[8][8];
#pragma unroll
    for (int i = 0; i < 8; i++)
#pragma unroll
        for (int j = 0; j < 8; j++) acc[i][j] = 0.f;

    for (int k0 = 0; k0 < D; k0 += BK) {
        const float4 av = *(const float4*)(X + (size_t)(m0 + lrow) * D + k0 + lcol4);
        const float4 bv = *(const float4*)(W + (size_t)(n0 + lrow) * D + k0 + lcol4);
        __syncthreads();   // previous iteration's smem reads done
        sA[lcol4 + 0][lrow] = av.x;
        sA[lcol4 + 1][lrow] = av.y;
        sA[lcol4 + 2][lrow] = av.z;
        sA[lcol4 + 3][lrow] = av.w;
        sB[lcol4 + 0][lrow] = bv.x;
        sB[lcol4 + 1][lrow] = bv.y;
        sB[lcol4 + 2][lrow] = bv.z;
        sB[lcol4 + 3][lrow] = bv.w;
        __syncthreads();

#pragma unroll
        for (int kk = 0; kk < BK; kk++) {
            float a[8], bb[8];
            const float4 a0 = *(const float4*)&sA[kk][ty * 8 + 0];
            const float4 a1 = *(const float4*)&sA[kk][ty * 8 + 4];
            const float4 b0 = *(const float4*)&sB[kk][tx * 8 + 0];
            const float4 b1 = *(const float4*)&sB[kk][tx * 8 + 4];
            a[0]=a0.x; a[1]=a0.y; a[2]=a0.z; a[3]=a0.w;
            a[4]=a1.x; a[5]=a1.y; a[6]=a1.z; a[7]=a1.w;
            bb[0]=b0.x; bb[1]=b0.y; bb[2]=b0.z; bb[3]=b0.w;
            bb[4]=b1.x; bb[5]=b1.y; bb[6]=b1.z; bb[7]=b1.w;
#pragma unroll
            for (int i = 0; i < 8; i++)
#pragma unroll
                for (int j = 0; j < 8; j++)
                    acc[i][j] += a[i] * bb[j];
        }
    }

    // Epilogue scatter. BN=128 divides 512 -> 'which' is constant per block.
    const int which = n0 / 512;   // 0=Q, 1=K, 2=V
    float* dst = (which == 0) ? g_Q : (which == 1) ? g_K : g_V;

#pragma unroll
    for (int i = 0; i < 8; i++) {
        const int m  = m0 + ty * 8 + i;
        const int b  = m >> 11;         // /2048
        const int n  = m & 2047;
#pragma unroll
        for (int j = 0; j < 8; j++) {
            const int c  = n0 + tx * 8 + j;
            const int h  = (c >> 6) & 7;
            const int dh = c & 63;
            dst[(((size_t)(b * H + h)) * N + n) * DH + dh] = acc[i][j];
        }
    }
}

// ---------------------------------------------------------------------------
// Kernel 2: flash-attention (fp32), one thread per query row.
// q_cross[t] = q[t-1] (t>0) handled at q load. Softmax over full N keys.
// K/V tiles of 32 keys x 64 dims in smem; broadcast reads (conflict-free).
// ---------------------------------------------------------------------------
constexpr int BQ   = 128;   // query rows per block == blockDim
constexpr int BKEY = 32;    // keys per tile

__global__ __launch_bounds__(BQ) void attn_kernel(float* __restrict__ out)
{
    const int tid = threadIdx.x;
    const int qr  = blockIdx.x * BQ + tid;
    const int h   = blockIdx.y;
    const int b   = blockIdx.z;
    const size_t base = ((size_t)(b * H + h)) * N * DH;

    // Shifted query
    const int qsrc = (qr == 0) ? 0 : qr - 1;
    float q[DH];
#pragma unroll
    for (int d = 0; d < DH; d += 4) {
        const float4 v = *(const float4*)(g_Q + base + (size_t)qsrc * DH + d);
        q[d + 0] = v.x * SCALE;
        q[d + 1] = v.y * SCALE;
        q[d + 2] = v.z * SCALE;
        q[d + 3] = v.w * SCALE;
    }

    float acc[DH];
#pragma unroll
    for (int d = 0; d < DH; d++) acc[d] = 0.f;
    float mval = -1e30f;
    float lsum = 0.f;

    __shared__ float4 sK[BKEY][DH / 4];
    __shared__ float4 sV[BKEY][DH / 4];

    for (int kt = 0; kt < N; kt += BKEY) {
        __syncthreads();
        // 32*16 = 512 float4 per array; 128 threads -> 4 each, coalesced
#pragma unroll
        for (int i = 0; i < 4; i++) {
            const int idx = tid + i * BQ;   // 0..511
            const int row = idx >> 4;
            const int col = idx & 15;
            sK[row][col] = *(const float4*)(g_K + base + (size_t)(kt + row) * DH + col * 4);
            sV[row][col] = *(const float4*)(g_V + base + (size_t)(kt + row) * DH + col * 4);
        }
        __syncthreads();

        float s[BKEY];
        float mt = mval;
#pragma unroll
        for (int j = 0; j < BKEY; j++) {
            float sum = 0.f;
#pragma unroll
            for (int c = 0; c < DH / 4; c++) {
                const float4 kv = sK[j][c];
                sum += q[4 * c + 0] * kv.x;
                sum += q[4 * c + 1] * kv.y;
                sum += q[4 * c + 2] * kv.z;
                sum += q[4 * c + 3] * kv.w;
            }
            s[j] = sum;
            mt = fmaxf(mt, sum);
        }

        const float corr = __expf(mval - mt);
        mval = mt;
        lsum *= corr;
#pragma unroll
        for (int d = 0; d < DH; d++) acc[d] *= corr;

#pragma unroll
        for (int j = 0; j < BKEY; j++) {
            const float p = __expf(s[j] - mval);
            lsum += p;
#pragma unroll
            for (int c = 0; c < DH / 4; c++) {
                const float4 vv = sV[j][c];
                acc[4 * c + 0] += p * vv.x;
                acc[4 * c + 1] += p * vv.y;
                acc[4 * c + 2] += p * vv.z;
                acc[4 * c + 3] += p * vv.w;
            }
        }
    }

    const float inv = 1.0f / lsum;
    float* op = out + ((size_t)(b * N + qr)) * (H * DH) + h * DH;
#pragma unroll
    for (int d = 0; d < DH; d += 4) {
        float4 v;
        v.x = acc[d + 0] * inv;
        v.y = acc[d + 1] * inv;
        v.z = acc[d + 2] * inv;
        v.w = acc[d + 3] * inv;
        *(float4*)(op + d) = v;
    }
}

// ---------------------------------------------------------------------------
extern "C" void kernel_launch(void* const* d_in, const int* in_sizes, int n_in,
                              void* d_out, int out_size)
{
    const float* x = (const float*)d_in[0];   // [4, 2048, 512] fp32
    const float* w = (const float*)d_in[1];   // [1536, 512] fp32
    float* out     = (float*)d_out;           // [4, 2048, 512] fp32

    dim3 g1(QKV_COLS / 128, M_ROWS / 128);    // (12, 64)
    qkv_gemm<<<g1, 256>>>(x, w);

    dim3 g2(N / BQ, H, B);                    // (16, 8, 4)
    attn_kernel<<<g2, BQ>>>(out);
}